// round 16
// baseline (speedup 1.0000x reference)
#include <cuda_runtime.h>
#include <cuda_bf16.h>
#include <stdint.h>

#define Bn 8192
#define KSTEPS 10
#define STG 30720            // per-stage smem: A 10240 + Bhi 10240 + Blo 10240
#define SMEM_SZ (3 * STG)

__device__ __nv_bfloat16 g_A1[Bn * 1024];    // chain state vn (binary)
__device__ __nv_bfloat16 g_h16[Bn * 1024];   // hidden samples
__device__ __nv_bfloat16 g_vd16[Bn * 1024];  // v_data
__device__ __nv_bfloat16 g_B1[1024 * 2048];  // [h][v]: W^T hi | lo
__device__ __nv_bfloat16 g_B2[1024 * 2048];  // [v][h]: W hi | lo
__device__ float    g_fpart[Bn * 48];        // FE partials: 16 slots x {sp1, sp2, vb}
__device__ float    g_wpart[32 * 1024];      // wcol partials
__device__ float    g_wcol[1024];
__device__ float    g_u[Bn];
__device__ float    g_bsum;
__device__ uint32_t g_keys[2 + 6 * KSTEPS];
__device__ double   g_acc[2];

// ------------------------------ threefry -----------------------------------
__device__ __forceinline__ uint32_t rotl_(uint32_t x, int r) {
    return (x << r) | (x >> (32 - r));
}
__device__ __forceinline__ void tf2x32(uint32_t k0, uint32_t k1, uint32_t x0,
                                       uint32_t x1, uint32_t& o0, uint32_t& o1) {
    uint32_t ks2 = k0 ^ k1 ^ 0x1BD11BDAu;
    x0 += k0; x1 += k1;
#define TF_R4(a,b,c,d) \
    x0 += x1; x1 = rotl_(x1, a); x1 ^= x0; \
    x0 += x1; x1 = rotl_(x1, b); x1 ^= x0; \
    x0 += x1; x1 = rotl_(x1, c); x1 ^= x0; \
    x0 += x1; x1 = rotl_(x1, d); x1 ^= x0;
    TF_R4(13, 15, 26, 6)
    x0 += k1;  x1 += ks2 + 1u;
    TF_R4(17, 29, 16, 24)
    x0 += ks2; x1 += k0 + 2u;
    TF_R4(13, 15, 26, 6)
    x0 += k0;  x1 += k1 + 3u;
    TF_R4(17, 29, 16, 24)
    x0 += k1;  x1 += ks2 + 4u;
    TF_R4(13, 15, 26, 6)
    x0 += ks2; x1 += k0 + 5u;
#undef TF_R4
    o0 = x0; o1 = x1;
}
__device__ __forceinline__ uint32_t rbits(uint32_t ka, uint32_t kb, uint32_t i) {
    uint32_t o0, o1;
    tf2x32(ka, kb, 0u, i, o0, o1);
    return o0 ^ o1;
}
__device__ __forceinline__ float u01(uint32_t b) {
    return __uint_as_float((b >> 9) | 0x3F800000u) - 1.0f;
}
__device__ __forceinline__ float sigm(float x) { return 1.0f / (1.0f + expf(-x)); }
__device__ __forceinline__ float softp(float x) {
    return fmaxf(x, 0.0f) + log1pf(expf(-fabsf(x)));
}
__device__ __forceinline__ float warpSum(float v) {
#pragma unroll
    for (int o = 16; o; o >>= 1) v += __shfl_down_sync(0xffffffffu, v, o);
    return v;
}

// ------------------------------ mma helpers --------------------------------
__device__ __forceinline__ uint32_t cvta_s(const void* p) {
    uint32_t a;
    asm("{.reg .u64 t; cvta.to.shared.u64 t, %1; cvt.u32.u64 %0, t;}" : "=r"(a) : "l"(p));
    return a;
}
__device__ __forceinline__ void ldm4(uint32_t& r0, uint32_t& r1, uint32_t& r2,
                                     uint32_t& r3, uint32_t a) {
    asm volatile("ldmatrix.sync.aligned.m8n8.x4.shared.b16 {%0,%1,%2,%3},[%4];"
                 : "=r"(r0), "=r"(r1), "=r"(r2), "=r"(r3) : "r"(a));
}
__device__ __forceinline__ void mma16816(float* d, const uint32_t* a, const uint32_t* b) {
    asm volatile(
        "mma.sync.aligned.m16n8k16.row.col.f32.bf16.bf16.f32 "
        "{%0,%1,%2,%3},{%4,%5,%6,%7},{%8,%9},{%0,%1,%2,%3};"
        : "+f"(d[0]), "+f"(d[1]), "+f"(d[2]), "+f"(d[3])
        : "r"(a[0]), "r"(a[1]), "r"(a[2]), "r"(a[3]), "r"(b[0]), "r"(b[1]));
}
__device__ __forceinline__ void cpa16(uint32_t s, const void* g) {
    asm volatile("cp.async.cg.shared.global [%0],[%1],16;" :: "r"(s), "l"(g));
}
#define CPCOMMIT() asm volatile("cp.async.commit_group;")
#define CPWAIT(n)  asm volatile("cp.async.wait_group %0;" :: "n"(n) : "memory")

// -------- GEMM: C[8192,1024] = A[8192,1024] @ (B_hi+B_lo)[1024,1024]^T ------
// Round-6 config: 4m x 2n warps, K-chunk 32, 3-stage ring, occ 2.
// Change vs round 15: next-stage LOADSTAGE issued BEFORE the compute block
// (after the wait+barrier), keeping two stages of cp.async in flight during
// every compute window instead of one.
// MODE 0: sample bernoulli(sigm(C + bias1)) -> outp (bf16 0/1), keys at koff.
// MODE 3: FE partials {softplus sums, v.b} -> part (bias1=b, bias2=c, v=A).
template <int MODE>
__global__ __launch_bounds__(256, 2) void k_mma(const __nv_bfloat16* __restrict__ A,
                                                const __nv_bfloat16* __restrict__ Bm,
                                                __nv_bfloat16* __restrict__ outp,
                                                const float* __restrict__ bias1,
                                                const float* __restrict__ bias2,
                                                float* __restrict__ part, int koff) {
    extern __shared__ char smem[];
    const uint32_t sbase = cvta_s(smem);
    const int tid = threadIdx.x, lane = tid & 31, wid = tid >> 5;
    const int wm = wid >> 1, wn = wid & 1;
    const int bM = blockIdx.y, bN = blockIdx.x;

    const int arow = wm * 32 + (lane & 7) + ((lane & 8) ? 8 : 0);
    const int acol = ((lane & 16) ? 8 : 0);
    const int brow = wn * 64 + (lane & 7) + ((lane & 16) ? 8 : 0);
    const int bcol = ((lane & 8) ? 8 : 0);

    float acc[2][8][4];
#pragma unroll
    for (int m = 0; m < 2; m++)
#pragma unroll
        for (int n = 0; n < 8; n++)
#pragma unroll
            for (int q = 0; q < 4; q++) acc[m][n][q] = 0.0f;

#define LOADSTAGE(st, k0) { \
    uint32_t db = sbase + (uint32_t)(st) * STG; \
    _Pragma("unroll") \
    for (int it = 0; it < 2; it++) { \
        int idx = it * 256 + tid, r = idx >> 2, c16 = idx & 3; \
        uint32_t so = (uint32_t)(r * 80 + c16 * 16); \
        const __nv_bfloat16* ag = A  + (size_t)(bM * 128 + r) * 1024 + (k0) + c16 * 8; \
        const __nv_bfloat16* bg = Bm + (size_t)(bN * 128 + r) * 2048 + (k0) + c16 * 8; \
        cpa16(db + so, ag); \
        cpa16(db + 10240 + so, bg); \
        cpa16(db + 20480 + so, bg + 1024); \
    } \
    CPCOMMIT(); }

    LOADSTAGE(0, 0)
    LOADSTAGE(1, 32)
    for (int i = 0; i < 32; i++) {
        if (i < 31) CPWAIT(1); else CPWAIT(0);
        __syncthreads();
        // issue next-stage loads FIRST: two stages in flight during compute
        if (i < 30) { LOADSTAGE((i + 2) % 3, (i + 2) * 32) }
        uint32_t sb = sbase + (uint32_t)(i % 3) * STG;
#pragma unroll
        for (int ks = 0; ks < 32; ks += 16) {
            uint32_t Af[2][4], Bf[8][2];
#pragma unroll
            for (int mt = 0; mt < 2; mt++)
                ldm4(Af[mt][0], Af[mt][1], Af[mt][2], Af[mt][3],
                     sb + (arow + mt * 16) * 80 + (ks + acol) * 2);
            // hi
#pragma unroll
            for (int nb = 0; nb < 4; nb++)
                ldm4(Bf[2*nb][0], Bf[2*nb][1], Bf[2*nb+1][0], Bf[2*nb+1][1],
                     sb + 10240 + (brow + nb * 16) * 80 + (ks + bcol) * 2);
#pragma unroll
            for (int mt = 0; mt < 2; mt++)
#pragma unroll
                for (int nf = 0; nf < 8; nf++) mma16816(acc[mt][nf], Af[mt], Bf[nf]);
            // lo
#pragma unroll
            for (int nb = 0; nb < 4; nb++)
                ldm4(Bf[2*nb][0], Bf[2*nb][1], Bf[2*nb+1][0], Bf[2*nb+1][1],
                     sb + 20480 + (brow + nb * 16) * 80 + (ks + bcol) * 2);
#pragma unroll
            for (int mt = 0; mt < 2; mt++)
#pragma unroll
                for (int nf = 0; nf < 8; nf++) mma16816(acc[mt][nf], Af[mt], Bf[nf]);
        }
    }
#undef LOADSTAGE

    // ------------------------------ epilogue -------------------------------
    uint32_t ka = 0, kb = 0;
    if (MODE == 0) { ka = g_keys[koff]; kb = g_keys[koff + 1]; }
    const int lq = lane & 3, lr = lane >> 2;
#pragma unroll
    for (int mt = 0; mt < 2; mt++) {
#pragma unroll
        for (int h = 0; h < 2; h++) {
            int row = bM * 128 + wm * 32 + mt * 16 + lr + h * 8;
            if (MODE == 0) {
                if (h == 0) {
#pragma unroll
                    for (int nf = 0; nf < 8; nf++) {
                        int C0 = bN * 128 + wn * 64 + nf * 8 + lq * 2;
                        uint32_t i0 = (uint32_t)row * 1024u + (uint32_t)C0;
                        uint32_t i1 = i0 + 8 * 1024;
                        float b0 = bias1[C0], b1 = bias1[C0 + 1];
                        uint32_t p;
                        p  = (u01(rbits(ka, kb, i0))     < sigm(acc[mt][nf][0] + b0)) ? 0x3F80u : 0u;
                        p |= (u01(rbits(ka, kb, i0 + 1)) < sigm(acc[mt][nf][1] + b1)) ? 0x3F800000u : 0u;
                        *(uint32_t*)(outp + i0) = p;
                        p  = (u01(rbits(ka, kb, i1))     < sigm(acc[mt][nf][2] + b0)) ? 0x3F80u : 0u;
                        p |= (u01(rbits(ka, kb, i1 + 1)) < sigm(acc[mt][nf][3] + b1)) ? 0x3F800000u : 0u;
                        *(uint32_t*)(outp + i1) = p;
                    }
                }
            } else {            // MODE 3: free-energy partials
                float s0 = 0.0f, s1 = 0.0f, s2 = 0.0f;
#pragma unroll
                for (int nf = 0; nf < 8; nf++) {
                    int col = bN * 128 + wn * 64 + nf * 8 + lq * 2;
                    float a0 = acc[mt][nf][2*h], a1 = acc[mt][nf][2*h+1];
                    __nv_bfloat162 vv = *(const __nv_bfloat162*)(A + (size_t)row * 1024 + col);
                    float v0 = __bfloat162float(vv.x), v1 = __bfloat162float(vv.y);
                    float c0 = bias2[col], c1 = bias2[col + 1];
                    s0 += softp(a0 + c0) + softp(a1 + c1);
                    s1 += softp(g_wcol[col] - a0 + c0) + softp(g_wcol[col+1] - a1 + c1);
                    s2 += v0 * bias1[col] + v1 * bias1[col + 1];
                }
                s0 += __shfl_xor_sync(0xffffffffu, s0, 1);
                s0 += __shfl_xor_sync(0xffffffffu, s0, 2);
                s1 += __shfl_xor_sync(0xffffffffu, s1, 1);
                s1 += __shfl_xor_sync(0xffffffffu, s1, 2);
                s2 += __shfl_xor_sync(0xffffffffu, s2, 1);
                s2 += __shfl_xor_sync(0xffffffffu, s2, 2);
                if (lq == 0) {
                    float* dst = part + (size_t)row * 48 + (bN * 2 + wn) * 3;
                    dst[0] = s0; dst[1] = s1; dst[2] = s2;
                }
            }
        }
    }
}

// ------------------------------ small kernels ------------------------------
__global__ void k_keys(const int* __restrict__ seed) {
    if (threadIdx.x != 0 || blockIdx.x != 0) return;
    uint32_t ck0 = 0u, ck1 = (uint32_t)seed[0], a, b, o0, o1;
    tf2x32(ck0, ck1, 0u, 0u, o0, o1);
    tf2x32(ck0, ck1, 0u, 1u, a, b);
    g_keys[0] = a; g_keys[1] = b; ck0 = o0; ck1 = o1;
    for (int t = 0; t < KSTEPS; t++) {
        uint32_t n0, n1;
        tf2x32(ck0, ck1, 0u, 0u, n0, n1);
        tf2x32(ck0, ck1, 0u, 1u, a, b); g_keys[2+6*t+0] = a; g_keys[2+6*t+1] = b;
        tf2x32(ck0, ck1, 0u, 2u, a, b); g_keys[2+6*t+2] = a; g_keys[2+6*t+3] = b;
        tf2x32(ck0, ck1, 0u, 3u, a, b); g_keys[2+6*t+4] = a; g_keys[2+6*t+5] = b;
        ck0 = n0; ck1 = n1;
    }
}

__global__ void k_u0() {
    int i = blockIdx.x * 256 + threadIdx.x;
    g_u[i] = (u01(rbits(g_keys[0], g_keys[1], (uint32_t)i)) < 0.5f) ? 1.0f : 0.0f;
}

// v_data -> vd16, and A1 = u0 ? v : 1-v  (first v_branch)
__global__ void k_init(const float* __restrict__ vd) {
    int i = blockIdx.x * 256 + threadIdx.x;
    float v = vd[i];
    g_vd16[i] = __float2bfloat16(v);
    float u = g_u[i >> 10];
    g_A1[i] = __float2bfloat16((u != 0.0f) ? v : 1.0f - v);
}

// merged split: read W tile once, write B2 direct + B1 transposed (hi/lo)
__global__ void k_split(const float* __restrict__ W) {
    __shared__ float t[32][33];
    int x = blockIdx.x * 32 + threadIdx.x, y0 = blockIdx.y * 32;
    for (int j = threadIdx.y; j < 32; j += 8) {
        float w = W[(size_t)(y0 + j) * 1024 + x];
        t[j][threadIdx.x] = w;
        __nv_bfloat16 hi = __float2bfloat16(w);
        size_t o2 = (size_t)(y0 + j) * 2048 + x;      // B2[v][h]
        g_B2[o2] = hi;
        g_B2[o2 + 1024] = __float2bfloat16(w - __bfloat162float(hi));
    }
    __syncthreads();
    for (int j = threadIdx.y; j < 32; j += 8) {
        float w = t[threadIdx.x][j];
        int h = blockIdx.x * 32 + j, v = y0 + threadIdx.x;
        __nv_bfloat16 hi = __float2bfloat16(w);
        g_B1[(size_t)h * 2048 + v] = hi;
        g_B1[(size_t)h * 2048 + 1024 + v] = __float2bfloat16(w - __bfloat162float(hi));
    }
}

// wcol phase 1: partial sums over 32-row slabs (deterministic slots)
__global__ void k_wcol1(const float* __restrict__ W) {
    int h = blockIdx.x * 256 + threadIdx.x;
    int vb = blockIdx.y;
    float s = 0.0f;
#pragma unroll 8
    for (int v = vb * 32; v < vb * 32 + 32; v++) s += W[(size_t)v * 1024 + h];
    g_wpart[vb * 1024 + h] = s;
}
// wcol phase 2: fixed-order sum of 32 partials
__global__ void k_wcol2() {
    int h = blockIdx.x * 256 + threadIdx.x;
    float s = 0.0f;
#pragma unroll
    for (int k = 0; k < 32; k++) s += g_wpart[k * 1024 + h];
    g_wcol[h] = s;
}

__global__ void k_bsum(const float* __restrict__ b) {
    float s = 0.0f;
    for (int j = threadIdx.x; j < 1024; j += 256) s += b[j];
    __shared__ float sh[8];
    float w = warpSum(s);
    if ((threadIdx.x & 31) == 0) sh[threadIdx.x >> 5] = w;
    __syncthreads();
    if (threadIdx.x == 0) {
        float t = 0.0f;
        for (int k = 0; k < 8; k++) t += sh[k];
        g_bsum = t; g_acc[0] = 0.0; g_acc[1] = 0.0;
    }
}

// reduce FE partials -> F per row -> sum into g_acc[accIdx]
__global__ void k_fered(int accIdx) {
    int row = blockIdx.x * 256 + threadIdx.x;
    const float* p = g_fpart + (size_t)row * 48;
    float S1 = 0.0f, S2 = 0.0f, VB = 0.0f;
#pragma unroll
    for (int s = 0; s < 16; s++) { S1 += p[3*s]; S2 += p[3*s+1]; VB += p[3*s+2]; }
    float nfn = VB - S1, nff = (g_bsum - VB) - S2;
    float m = fmaxf(nfn, nff);
    double F = (double)(-(m + log1pf(expf(fminf(nfn, nff) - m))));
#pragma unroll
    for (int o = 16; o; o >>= 1) F += __shfl_down_sync(0xffffffffu, F, o);
    if ((threadIdx.x & 31) == 0) atomicAdd(&g_acc[accIdx], F);
}

__global__ void k_final(float* __restrict__ out) {
    if (threadIdx.x == 0 && blockIdx.x == 0)
        out[0] = (float)((g_acc[0] - g_acc[1]) * (1.0 / (double)Bn));
}

// ------------------------------ launch -------------------------------------
extern "C" void kernel_launch(void* const* d_in, const int* in_sizes, int n_in,
                              void* d_out, int out_size) {
    const float* v_data = (const float*)d_in[0];
    const float* W      = (const float*)d_in[1];
    const float* b      = (const float*)d_in[2];
    const float* c      = (const float*)d_in[3];
    const int*   seed   = (const int*)d_in[4];
    float* out = (float*)d_out;

    __nv_bfloat16 *pA1, *pH, *pVd, *pB1, *pB2;
    float *pFpart;
    cudaGetSymbolAddress((void**)&pA1, g_A1);
    cudaGetSymbolAddress((void**)&pH,  g_h16);
    cudaGetSymbolAddress((void**)&pVd, g_vd16);
    cudaGetSymbolAddress((void**)&pB1, g_B1);
    cudaGetSymbolAddress((void**)&pB2, g_B2);
    cudaGetSymbolAddress((void**)&pFpart, g_fpart);

    cudaFuncSetAttribute(k_mma<0>, cudaFuncAttributeMaxDynamicSharedMemorySize, SMEM_SZ);
    cudaFuncSetAttribute(k_mma<3>, cudaFuncAttributeMaxDynamicSharedMemorySize, SMEM_SZ);

    dim3 gg(8, 64);
    k_keys<<<1, 32>>>(seed);
    k_u0<<<Bn / 256, 256>>>();
    k_init<<<Bn * 1024 / 256, 256>>>(v_data);
    k_split<<<dim3(32, 32), dim3(32, 8)>>>(W);
    k_wcol1<<<dim3(4, 32), 256>>>(W);
    k_wcol2<<<4, 256>>>();
    k_bsum<<<1, 256>>>(b);

    for (int t = 0; t < KSTEPS; t++) {
        int koff = 2 + 6 * t;
        // h  = bern(sigm(vn @ W + c))       keys k1
        k_mma<0><<<gg, 256, SMEM_SZ>>>(pA1, pB1, pH, c, nullptr, nullptr, koff);
        // vn = bern(sigm(h @ W^T + b))      keys k3  (u-chain provably dead)
        k_mma<0><<<gg, 256, SMEM_SZ>>>(pH, pB2, pA1, b, nullptr, nullptr, koff + 4);
    }

    // free energies (fused partial epilogue): F(v_model) = F(vn) by symmetry
    k_mma<3><<<gg, 256, SMEM_SZ>>>(pVd, pB1, nullptr, b, c, pFpart, 0);
    k_fered<<<Bn / 256, 256>>>(0);
    k_mma<3><<<gg, 256, SMEM_SZ>>>(pA1, pB1, nullptr, b, c, pFpart, 0);
    k_fered<<<Bn / 256, 256>>>(1);
    k_final<<<1, 1>>>(out);
}

// round 17
// speedup vs baseline: 1.0894x; 1.0894x over previous
#include <cuda_runtime.h>
#include <cuda_bf16.h>
#include <stdint.h>

#define Bn 8192
#define KSTEPS 10
#define STG 30720            // per-stage smem: A 10240 + Bhi 10240 + Blo 10240
#define SMEM_SZ (3 * STG)

__device__ __nv_bfloat16 g_A1[Bn * 1024];    // chain state vn (binary)
__device__ __nv_bfloat16 g_h16[Bn * 1024];   // hidden samples
__device__ __nv_bfloat16 g_vd16[Bn * 1024];  // v_data
__device__ __nv_bfloat16 g_B1[1024 * 2048];  // [h][v]: W^T hi | lo
__device__ __nv_bfloat16 g_B2[1024 * 2048];  // [v][h]: W hi | lo
__device__ float    g_fpart[Bn * 48];        // FE partials: 16 slots x {sp1, sp2, vb}
__device__ float    g_wpart[32 * 1024];      // wcol partials
__device__ float    g_wcol[1024];
__device__ float    g_u[Bn];
__device__ float    g_bsum;
__device__ uint32_t g_keys[2 + 6 * KSTEPS];
__device__ double   g_acc[2];

// ------------------------------ threefry -----------------------------------
__device__ __forceinline__ uint32_t rotl_(uint32_t x, int r) {
    return (x << r) | (x >> (32 - r));
}
__device__ __forceinline__ void tf2x32(uint32_t k0, uint32_t k1, uint32_t x0,
                                       uint32_t x1, uint32_t& o0, uint32_t& o1) {
    uint32_t ks2 = k0 ^ k1 ^ 0x1BD11BDAu;
    x0 += k0; x1 += k1;
#define TF_R4(a,b,c,d) \
    x0 += x1; x1 = rotl_(x1, a); x1 ^= x0; \
    x0 += x1; x1 = rotl_(x1, b); x1 ^= x0; \
    x0 += x1; x1 = rotl_(x1, c); x1 ^= x0; \
    x0 += x1; x1 = rotl_(x1, d); x1 ^= x0;
    TF_R4(13, 15, 26, 6)
    x0 += k1;  x1 += ks2 + 1u;
    TF_R4(17, 29, 16, 24)
    x0 += ks2; x1 += k0 + 2u;
    TF_R4(13, 15, 26, 6)
    x0 += k0;  x1 += k1 + 3u;
    TF_R4(17, 29, 16, 24)
    x0 += k1;  x1 += ks2 + 4u;
    TF_R4(13, 15, 26, 6)
    x0 += ks2; x1 += k0 + 5u;
#undef TF_R4
    o0 = x0; o1 = x1;
}
__device__ __forceinline__ uint32_t rbits(uint32_t ka, uint32_t kb, uint32_t i) {
    uint32_t o0, o1;
    tf2x32(ka, kb, 0u, i, o0, o1);
    return o0 ^ o1;
}
__device__ __forceinline__ float u01(uint32_t b) {
    return __uint_as_float((b >> 9) | 0x3F800000u) - 1.0f;
}
__device__ __forceinline__ float sigm(float x) { return 1.0f / (1.0f + expf(-x)); }
__device__ __forceinline__ float softp(float x) {
    return fmaxf(x, 0.0f) + log1pf(expf(-fabsf(x)));
}
__device__ __forceinline__ float warpSum(float v) {
#pragma unroll
    for (int o = 16; o; o >>= 1) v += __shfl_down_sync(0xffffffffu, v, o);
    return v;
}

// ------------------------------ mma helpers --------------------------------
__device__ __forceinline__ uint32_t cvta_s(const void* p) {
    uint32_t a;
    asm("{.reg .u64 t; cvta.to.shared.u64 t, %1; cvt.u32.u64 %0, t;}" : "=r"(a) : "l"(p));
    return a;
}
__device__ __forceinline__ void ldm4(uint32_t& r0, uint32_t& r1, uint32_t& r2,
                                     uint32_t& r3, uint32_t a) {
    asm volatile("ldmatrix.sync.aligned.m8n8.x4.shared.b16 {%0,%1,%2,%3},[%4];"
                 : "=r"(r0), "=r"(r1), "=r"(r2), "=r"(r3) : "r"(a));
}
__device__ __forceinline__ void mma16816(float* d, const uint32_t* a, const uint32_t* b) {
    asm volatile(
        "mma.sync.aligned.m16n8k16.row.col.f32.bf16.bf16.f32 "
        "{%0,%1,%2,%3},{%4,%5,%6,%7},{%8,%9},{%0,%1,%2,%3};"
        : "+f"(d[0]), "+f"(d[1]), "+f"(d[2]), "+f"(d[3])
        : "r"(a[0]), "r"(a[1]), "r"(a[2]), "r"(a[3]), "r"(b[0]), "r"(b[1]));
}
__device__ __forceinline__ void cpa16(uint32_t s, const void* g) {
    asm volatile("cp.async.cg.shared.global [%0],[%1],16;" :: "r"(s), "l"(g));
}
#define CPCOMMIT() asm volatile("cp.async.commit_group;")
#define CPWAIT(n)  asm volatile("cp.async.wait_group %0;" :: "n"(n) : "memory")

// -------- GEMM: C[8192,1024] = A[8192,1024] @ (B_hi+B_lo)[1024,1024]^T ------
// Round-6 config verbatim: 4m x 2n warps, K-chunk 32, 3-stage ring, occ 2,
// load-issue AFTER compute (measured optimum).
// MODE 0: sample bernoulli(sigm(C + bias1)) -> outp (bf16 0/1), keys at koff.
// MODE 3: FE partials {softplus sums, v.b} -> part (bias1=b, bias2=c, v=A).
template <int MODE>
__global__ __launch_bounds__(256, 2) void k_mma(const __nv_bfloat16* __restrict__ A,
                                                const __nv_bfloat16* __restrict__ Bm,
                                                __nv_bfloat16* __restrict__ outp,
                                                const float* __restrict__ bias1,
                                                const float* __restrict__ bias2,
                                                float* __restrict__ part, int koff) {
    extern __shared__ char smem[];
    const uint32_t sbase = cvta_s(smem);
    const int tid = threadIdx.x, lane = tid & 31, wid = tid >> 5;
    const int wm = wid >> 1, wn = wid & 1;
    const int bM = blockIdx.y, bN = blockIdx.x;

    const int arow = wm * 32 + (lane & 7) + ((lane & 8) ? 8 : 0);
    const int acol = ((lane & 16) ? 8 : 0);
    const int brow = wn * 64 + (lane & 7) + ((lane & 16) ? 8 : 0);
    const int bcol = ((lane & 8) ? 8 : 0);

    float acc[2][8][4];
#pragma unroll
    for (int m = 0; m < 2; m++)
#pragma unroll
        for (int n = 0; n < 8; n++)
#pragma unroll
            for (int q = 0; q < 4; q++) acc[m][n][q] = 0.0f;

#define LOADSTAGE(st, k0) { \
    uint32_t db = sbase + (uint32_t)(st) * STG; \
    _Pragma("unroll") \
    for (int it = 0; it < 2; it++) { \
        int idx = it * 256 + tid, r = idx >> 2, c16 = idx & 3; \
        uint32_t so = (uint32_t)(r * 80 + c16 * 16); \
        const __nv_bfloat16* ag = A  + (size_t)(bM * 128 + r) * 1024 + (k0) + c16 * 8; \
        const __nv_bfloat16* bg = Bm + (size_t)(bN * 128 + r) * 2048 + (k0) + c16 * 8; \
        cpa16(db + so, ag); \
        cpa16(db + 10240 + so, bg); \
        cpa16(db + 20480 + so, bg + 1024); \
    } \
    CPCOMMIT(); }

    LOADSTAGE(0, 0)
    LOADSTAGE(1, 32)
    for (int i = 0; i < 32; i++) {
        if (i < 31) CPWAIT(1); else CPWAIT(0);
        __syncthreads();
        uint32_t sb = sbase + (uint32_t)(i % 3) * STG;
#pragma unroll
        for (int ks = 0; ks < 32; ks += 16) {
            uint32_t Af[2][4], Bf[8][2];
#pragma unroll
            for (int mt = 0; mt < 2; mt++)
                ldm4(Af[mt][0], Af[mt][1], Af[mt][2], Af[mt][3],
                     sb + (arow + mt * 16) * 80 + (ks + acol) * 2);
            // hi
#pragma unroll
            for (int nb = 0; nb < 4; nb++)
                ldm4(Bf[2*nb][0], Bf[2*nb][1], Bf[2*nb+1][0], Bf[2*nb+1][1],
                     sb + 10240 + (brow + nb * 16) * 80 + (ks + bcol) * 2);
#pragma unroll
            for (int mt = 0; mt < 2; mt++)
#pragma unroll
                for (int nf = 0; nf < 8; nf++) mma16816(acc[mt][nf], Af[mt], Bf[nf]);
            // lo
#pragma unroll
            for (int nb = 0; nb < 4; nb++)
                ldm4(Bf[2*nb][0], Bf[2*nb][1], Bf[2*nb+1][0], Bf[2*nb+1][1],
                     sb + 20480 + (brow + nb * 16) * 80 + (ks + bcol) * 2);
#pragma unroll
            for (int mt = 0; mt < 2; mt++)
#pragma unroll
                for (int nf = 0; nf < 8; nf++) mma16816(acc[mt][nf], Af[mt], Bf[nf]);
        }
        if (i < 30) { LOADSTAGE((i + 2) % 3, (i + 2) * 32) }
    }
#undef LOADSTAGE

    // ------------------------------ epilogue -------------------------------
    uint32_t ka = 0, kb = 0;
    if (MODE == 0) { ka = g_keys[koff]; kb = g_keys[koff + 1]; }
    const int lq = lane & 3, lr = lane >> 2;
#pragma unroll
    for (int mt = 0; mt < 2; mt++) {
#pragma unroll
        for (int h = 0; h < 2; h++) {
            int row = bM * 128 + wm * 32 + mt * 16 + lr + h * 8;
            if (MODE == 0) {
                if (h == 0) {
#pragma unroll
                    for (int nf = 0; nf < 8; nf++) {
                        int C0 = bN * 128 + wn * 64 + nf * 8 + lq * 2;
                        uint32_t i0 = (uint32_t)row * 1024u + (uint32_t)C0;
                        uint32_t i1 = i0 + 8 * 1024;
                        float b0 = bias1[C0], b1 = bias1[C0 + 1];
                        uint32_t p;
                        p  = (u01(rbits(ka, kb, i0))     < sigm(acc[mt][nf][0] + b0)) ? 0x3F80u : 0u;
                        p |= (u01(rbits(ka, kb, i0 + 1)) < sigm(acc[mt][nf][1] + b1)) ? 0x3F800000u : 0u;
                        *(uint32_t*)(outp + i0) = p;
                        p  = (u01(rbits(ka, kb, i1))     < sigm(acc[mt][nf][2] + b0)) ? 0x3F80u : 0u;
                        p |= (u01(rbits(ka, kb, i1 + 1)) < sigm(acc[mt][nf][3] + b1)) ? 0x3F800000u : 0u;
                        *(uint32_t*)(outp + i1) = p;
                    }
                }
            } else {            // MODE 3: free-energy partials
                float s0 = 0.0f, s1 = 0.0f, s2 = 0.0f;
#pragma unroll
                for (int nf = 0; nf < 8; nf++) {
                    int col = bN * 128 + wn * 64 + nf * 8 + lq * 2;
                    float a0 = acc[mt][nf][2*h], a1 = acc[mt][nf][2*h+1];
                    __nv_bfloat162 vv = *(const __nv_bfloat162*)(A + (size_t)row * 1024 + col);
                    float v0 = __bfloat162float(vv.x), v1 = __bfloat162float(vv.y);
                    float c0 = bias2[col], c1 = bias2[col + 1];
                    s0 += softp(a0 + c0) + softp(a1 + c1);
                    s1 += softp(g_wcol[col] - a0 + c0) + softp(g_wcol[col+1] - a1 + c1);
                    s2 += v0 * bias1[col] + v1 * bias1[col + 1];
                }
                s0 += __shfl_xor_sync(0xffffffffu, s0, 1);
                s0 += __shfl_xor_sync(0xffffffffu, s0, 2);
                s1 += __shfl_xor_sync(0xffffffffu, s1, 1);
                s1 += __shfl_xor_sync(0xffffffffu, s1, 2);
                s2 += __shfl_xor_sync(0xffffffffu, s2, 1);
                s2 += __shfl_xor_sync(0xffffffffu, s2, 2);
                if (lq == 0) {
                    float* dst = part + (size_t)row * 48 + (bN * 2 + wn) * 3;
                    dst[0] = s0; dst[1] = s1; dst[2] = s2;
                }
            }
        }
    }
}

// ------------------------------ small kernels ------------------------------
__global__ void k_keys(const int* __restrict__ seed) {
    if (threadIdx.x != 0 || blockIdx.x != 0) return;
    uint32_t ck0 = 0u, ck1 = (uint32_t)seed[0], a, b, o0, o1;
    tf2x32(ck0, ck1, 0u, 0u, o0, o1);
    tf2x32(ck0, ck1, 0u, 1u, a, b);
    g_keys[0] = a; g_keys[1] = b; ck0 = o0; ck1 = o1;
    for (int t = 0; t < KSTEPS; t++) {
        uint32_t n0, n1;
        tf2x32(ck0, ck1, 0u, 0u, n0, n1);
        tf2x32(ck0, ck1, 0u, 1u, a, b); g_keys[2+6*t+0] = a; g_keys[2+6*t+1] = b;
        tf2x32(ck0, ck1, 0u, 2u, a, b); g_keys[2+6*t+2] = a; g_keys[2+6*t+3] = b;
        tf2x32(ck0, ck1, 0u, 3u, a, b); g_keys[2+6*t+4] = a; g_keys[2+6*t+5] = b;
        ck0 = n0; ck1 = n1;
    }
}

__global__ void k_u0() {
    int i = blockIdx.x * 256 + threadIdx.x;
    g_u[i] = (u01(rbits(g_keys[0], g_keys[1], (uint32_t)i)) < 0.5f) ? 1.0f : 0.0f;
}

// v_data -> vd16, and A1 = u0 ? v : 1-v  (first v_branch)
__global__ void k_init(const float* __restrict__ vd) {
    int i = blockIdx.x * 256 + threadIdx.x;
    float v = vd[i];
    g_vd16[i] = __float2bfloat16(v);
    float u = g_u[i >> 10];
    g_A1[i] = __float2bfloat16((u != 0.0f) ? v : 1.0f - v);
}

// merged split: read W tile once, write B2 direct + B1 transposed (hi/lo)
__global__ void k_split(const float* __restrict__ W) {
    __shared__ float t[32][33];
    int x = blockIdx.x * 32 + threadIdx.x, y0 = blockIdx.y * 32;
    for (int j = threadIdx.y; j < 32; j += 8) {
        float w = W[(size_t)(y0 + j) * 1024 + x];
        t[j][threadIdx.x] = w;
        __nv_bfloat16 hi = __float2bfloat16(w);
        size_t o2 = (size_t)(y0 + j) * 2048 + x;      // B2[v][h]
        g_B2[o2] = hi;
        g_B2[o2 + 1024] = __float2bfloat16(w - __bfloat162float(hi));
    }
    __syncthreads();
    for (int j = threadIdx.y; j < 32; j += 8) {
        float w = t[threadIdx.x][j];
        int h = blockIdx.x * 32 + j, v = y0 + threadIdx.x;
        __nv_bfloat16 hi = __float2bfloat16(w);
        g_B1[(size_t)h * 2048 + v] = hi;
        g_B1[(size_t)h * 2048 + 1024 + v] = __float2bfloat16(w - __bfloat162float(hi));
    }
}

// wcol phase 1: partial sums over 32-row slabs (deterministic slots)
__global__ void k_wcol1(const float* __restrict__ W) {
    int h = blockIdx.x * 256 + threadIdx.x;
    int vb = blockIdx.y;
    float s = 0.0f;
#pragma unroll 8
    for (int v = vb * 32; v < vb * 32 + 32; v++) s += W[(size_t)v * 1024 + h];
    g_wpart[vb * 1024 + h] = s;
}
// wcol phase 2: fixed-order sum of 32 partials
__global__ void k_wcol2() {
    int h = blockIdx.x * 256 + threadIdx.x;
    float s = 0.0f;
#pragma unroll
    for (int k = 0; k < 32; k++) s += g_wpart[k * 1024 + h];
    g_wcol[h] = s;
}

__global__ void k_bsum(const float* __restrict__ b) {
    float s = 0.0f;
    for (int j = threadIdx.x; j < 1024; j += 256) s += b[j];
    __shared__ float sh[8];
    float w = warpSum(s);
    if ((threadIdx.x & 31) == 0) sh[threadIdx.x >> 5] = w;
    __syncthreads();
    if (threadIdx.x == 0) {
        float t = 0.0f;
        for (int k = 0; k < 8; k++) t += sh[k];
        g_bsum = t; g_acc[0] = 0.0; g_acc[1] = 0.0;
    }
}

// reduce FE partials -> F per row -> sum into g_acc[accIdx]
__global__ void k_fered(int accIdx) {
    int row = blockIdx.x * 256 + threadIdx.x;
    const float* p = g_fpart + (size_t)row * 48;
    float S1 = 0.0f, S2 = 0.0f, VB = 0.0f;
#pragma unroll
    for (int s = 0; s < 16; s++) { S1 += p[3*s]; S2 += p[3*s+1]; VB += p[3*s+2]; }
    float nfn = VB - S1, nff = (g_bsum - VB) - S2;
    float m = fmaxf(nfn, nff);
    double F = (double)(-(m + log1pf(expf(fminf(nfn, nff) - m))));
#pragma unroll
    for (int o = 16; o; o >>= 1) F += __shfl_down_sync(0xffffffffu, F, o);
    if ((threadIdx.x & 31) == 0) atomicAdd(&g_acc[accIdx], F);
}

__global__ void k_final(float* __restrict__ out) {
    if (threadIdx.x == 0 && blockIdx.x == 0)
        out[0] = (float)((g_acc[0] - g_acc[1]) * (1.0 / (double)Bn));
}

// ------------------------------ launch -------------------------------------
extern "C" void kernel_launch(void* const* d_in, const int* in_sizes, int n_in,
                              void* d_out, int out_size) {
    const float* v_data = (const float*)d_in[0];
    const float* W      = (const float*)d_in[1];
    const float* b      = (const float*)d_in[2];
    const float* c      = (const float*)d_in[3];
    const int*   seed   = (const int*)d_in[4];
    float* out = (float*)d_out;

    __nv_bfloat16 *pA1, *pH, *pVd, *pB1, *pB2;
    float *pFpart;
    cudaGetSymbolAddress((void**)&pA1, g_A1);
    cudaGetSymbolAddress((void**)&pH,  g_h16);
    cudaGetSymbolAddress((void**)&pVd, g_vd16);
    cudaGetSymbolAddress((void**)&pB1, g_B1);
    cudaGetSymbolAddress((void**)&pB2, g_B2);
    cudaGetSymbolAddress((void**)&pFpart, g_fpart);

    cudaFuncSetAttribute(k_mma<0>, cudaFuncAttributeMaxDynamicSharedMemorySize, SMEM_SZ);
    cudaFuncSetAttribute(k_mma<3>, cudaFuncAttributeMaxDynamicSharedMemorySize, SMEM_SZ);

    dim3 gg(8, 64);
    k_keys<<<1, 32>>>(seed);
    k_u0<<<Bn / 256, 256>>>();
    k_init<<<Bn * 1024 / 256, 256>>>(v_data);
    k_split<<<dim3(32, 32), dim3(32, 8)>>>(W);
    k_wcol1<<<dim3(4, 32), 256>>>(W);
    k_wcol2<<<4, 256>>>();
    k_bsum<<<1, 256>>>(b);

    for (int t = 0; t < KSTEPS; t++) {
        int koff = 2 + 6 * t;
        // h  = bern(sigm(vn @ W + c))       keys k1
        k_mma<0><<<gg, 256, SMEM_SZ>>>(pA1, pB1, pH, c, nullptr, nullptr, koff);
        // vn = bern(sigm(h @ W^T + b))      keys k3  (u-chain provably dead)
        k_mma<0><<<gg, 256, SMEM_SZ>>>(pH, pB2, pA1, b, nullptr, nullptr, koff + 4);
    }

    // free energies (fused partial epilogue): F(v_model) = F(vn) by symmetry
    k_mma<3><<<gg, 256, SMEM_SZ>>>(pVd, pB1, nullptr, b, c, pFpart, 0);
    k_fered<<<Bn / 256, 256>>>(0);
    k_mma<3><<<gg, 256, SMEM_SZ>>>(pA1, pB1, nullptr, b, c, pFpart, 0);
    k_fered<<<Bn / 256, 256>>>(1);
    k_final<<<1, 1>>>(out);
}